// round 12
// baseline (speedup 1.0000x reference)
#include <cuda_runtime.h>
#include <cuda_fp16.h>
#include <cstdint>

#define FT_IN   40960
#define VFT_IN  640
#define FT_OUT  256
#define B_MAX   8192
#define CAP     128
#define OVF_MAX 4096

// -------- device-global scratch (no allocations allowed) --------
__device__ __half g_comb[(size_t)FT_IN * FT_OUT];   // [40960, 256] fp16: ftT + fftT[col%640]
__device__ float  g_fftT[(size_t)VFT_IN * FT_OUT];  // [640, 256]
__device__ float  g_bias[FT_OUT];                   // ft_b + fft_b
__device__ float  g_partial[2 * B_MAX];             // per-(side,row) dot partial
__device__ int    g_cnt[2 * B_MAX];
__device__ int2   g_bucket[2ULL * B_MAX * CAP];     // (col, val-bits)
__device__ int4   g_ovf[OVF_MAX];                   // (side, row, col, val-bits)
__device__ int    g_ovf_cnt;

// ---------------------------------------------------------------------------
// Prep: transpose fft_w [256,640] -> g_fftT [640,256]; zero counters; bias sum
// grid (20, 8) x block (32,8) = 40960 threads
// ---------------------------------------------------------------------------
__global__ void prep_kernel(const float* __restrict__ W,
                            const float* __restrict__ ft_b,
                            const float* __restrict__ fft_b) {
    __shared__ float tile[32][33];
    int colTile = blockIdx.x * 32;   // over 640
    int rowTile = blockIdx.y * 32;   // over 256
    int tx = threadIdx.x, ty = threadIdx.y;

    // folded housekeeping
    int gid = (blockIdx.y * gridDim.x + blockIdx.x) * 256 + ty * 32 + tx;
    if (gid < 2 * B_MAX) g_cnt[gid] = 0;
    if (gid == 0) g_ovf_cnt = 0;
    if (gid < FT_OUT) g_bias[gid] = ft_b[gid] + fft_b[gid];

    #pragma unroll
    for (int i = 0; i < 32; i += 8)
        tile[ty + i][tx] = W[(size_t)(rowTile + ty + i) * VFT_IN + colTile + tx];
    __syncthreads();
    #pragma unroll
    for (int i = 0; i < 32; i += 8) {
        int c = colTile + ty + i;
        int r = rowTile + tx;
        g_fftT[(size_t)c * FT_OUT + r] = tile[tx][ty + i];
    }
}

// ---------------------------------------------------------------------------
// Combine: transpose ft_w [256,40960] -> g_comb [40960,256] fp16,
// adding g_fftT[col%640]. half2 paired stores (4B coalesced).
// ---------------------------------------------------------------------------
__global__ void combine_kernel(const float* __restrict__ W) {
    __shared__ float tile[32][33];
    int colTile = blockIdx.x * 32;   // over 40960
    int rowTile = blockIdx.y * 32;   // over 256
    int tx = threadIdx.x, ty = threadIdx.y;
    #pragma unroll
    for (int i = 0; i < 32; i += 8)
        tile[ty + i][tx] = W[(size_t)(rowTile + ty + i) * FT_IN + colTile + tx];
    __syncthreads();

    int t = ty * 32 + tx;            // 0..255
    #pragma unroll
    for (int iter = 0; iter < 2; iter++) {
        int p  = t + iter * 256;     // 0..511 : 32 cols x 16 row-pairs
        int cl = p >> 4;             // column-local 0..31
        int rp = p & 15;             // row-pair 0..15
        int c  = colTile + cl;
        int r0 = rp * 2;             // local row (even)
        int cm = c % VFT_IN;
        float2 f = *reinterpret_cast<const float2*>(
            &g_fftT[(size_t)cm * FT_OUT + rowTile + r0]);
        __half2 h = __floats2half2_rn(tile[r0][cl] + f.x, tile[r0 + 1][cl] + f.y);
        *reinterpret_cast<__half2*>(&g_comb[(size_t)c * FT_OUT + rowTile + r0]) = h;
    }
}

// ---------------------------------------------------------------------------
// Binning: 4 entries per thread (int4/float4 loads) for MLP on the atomics
// ---------------------------------------------------------------------------
__global__ void bin_kernel(const int* __restrict__ stm_idx,
                           const int* __restrict__ nstm_idx,
                           const float* __restrict__ values,
                           int NNZ, int B) {
    int t = blockIdx.x * blockDim.x + threadIdx.x;
    int per_side = NNZ >> 2;
    if (t >= 2 * per_side) return;
    int side = (t >= per_side) ? 1 : 0;
    int base = (t - side * per_side) * 4;
    const int* idx = side ? nstm_idx : stm_idx;

    int4   rows = *reinterpret_cast<const int4*>(idx + base);
    int4   cols = *reinterpret_cast<const int4*>(idx + NNZ + base);
    float4 vals = *reinterpret_cast<const float4*>(values + base);

    int s0 = side * B + rows.x, s1 = side * B + rows.y;
    int s2 = side * B + rows.z, s3 = side * B + rows.w;
    int p0 = atomicAdd(&g_cnt[s0], 1);
    int p1 = atomicAdd(&g_cnt[s1], 1);
    int p2 = atomicAdd(&g_cnt[s2], 1);
    int p3 = atomicAdd(&g_cnt[s3], 1);

    if (p0 < CAP) g_bucket[(size_t)s0 * CAP + p0] = make_int2(cols.x, __float_as_int(vals.x));
    else { int o = atomicAdd(&g_ovf_cnt, 1); if (o < OVF_MAX) g_ovf[o] = make_int4(side, rows.x, cols.x, __float_as_int(vals.x)); }
    if (p1 < CAP) g_bucket[(size_t)s1 * CAP + p1] = make_int2(cols.y, __float_as_int(vals.y));
    else { int o = atomicAdd(&g_ovf_cnt, 1); if (o < OVF_MAX) g_ovf[o] = make_int4(side, rows.y, cols.y, __float_as_int(vals.y)); }
    if (p2 < CAP) g_bucket[(size_t)s2 * CAP + p2] = make_int2(cols.z, __float_as_int(vals.z));
    else { int o = atomicAdd(&g_ovf_cnt, 1); if (o < OVF_MAX) g_ovf[o] = make_int4(side, rows.z, cols.z, __float_as_int(vals.z)); }
    if (p3 < CAP) g_bucket[(size_t)s3 * CAP + p3] = make_int2(cols.w, __float_as_int(vals.w));
    else { int o = atomicAdd(&g_ovf_cnt, 1); if (o < OVF_MAX) g_ovf[o] = make_int4(side, rows.w, cols.w, __float_as_int(vals.w)); }
}

// ---------------------------------------------------------------------------
// Accumulate + fused head dot: one warp per (side,row).
// Lane owns 8 hidden units (one uint4 = 8 halves per column read).
// Entries broadcast across the warp via shfl, batches of 32.
// ---------------------------------------------------------------------------
__global__ void accumulate_kernel(const float* __restrict__ out_w, int B) {
    int warp_global = (blockIdx.x * blockDim.x + threadIdx.x) >> 5;
    int lane = threadIdx.x & 31;
    if (warp_global >= 2 * B) return;
    int slot = warp_global;
    int side = (slot >= B) ? 1 : 0;
    int row  = slot - side * B;

    int n = g_cnt[slot];
    if (n > CAP) n = CAP;

    float acc[8];
    {
        float4 b0 = *(reinterpret_cast<const float4*>(g_bias) + lane * 2);
        float4 b1 = *(reinterpret_cast<const float4*>(g_bias) + lane * 2 + 1);
        acc[0] = b0.x; acc[1] = b0.y; acc[2] = b0.z; acc[3] = b0.w;
        acc[4] = b1.x; acc[5] = b1.y; acc[6] = b1.z; acc[7] = b1.w;
    }

    const int2* bucket = g_bucket + (size_t)slot * CAP;
    for (int base = 0; base < n; base += 32) {
        int m = n - base; if (m > 32) m = 32;
        int2 ent = (lane < m) ? bucket[base + lane] : make_int2(0, 0);
        for (int e = 0; e < m; e++) {
            int   col = __shfl_sync(0xFFFFFFFFu, ent.x, e);
            float val = __int_as_float(__shfl_sync(0xFFFFFFFFu, ent.y, e));
            uint4 v = *reinterpret_cast<const uint4*>(
                g_comb + (size_t)col * FT_OUT + lane * 8);
            float2 c0 = __half22float2(*reinterpret_cast<__half2*>(&v.x));
            float2 c1 = __half22float2(*reinterpret_cast<__half2*>(&v.y));
            float2 c2 = __half22float2(*reinterpret_cast<__half2*>(&v.z));
            float2 c3 = __half22float2(*reinterpret_cast<__half2*>(&v.w));
            acc[0] = fmaf(val, c0.x, acc[0]);
            acc[1] = fmaf(val, c0.y, acc[1]);
            acc[2] = fmaf(val, c1.x, acc[2]);
            acc[3] = fmaf(val, c1.y, acc[3]);
            acc[4] = fmaf(val, c2.x, acc[4]);
            acc[5] = fmaf(val, c2.y, acc[5]);
            acc[6] = fmaf(val, c3.x, acc[6]);
            acc[7] = fmaf(val, c3.y, acc[7]);
        }
    }

    // Overflow fallback (normally g_ovf_cnt == 0)
    int novf = g_ovf_cnt;
    if (novf > 0) {
        if (novf > OVF_MAX) novf = OVF_MAX;
        for (int i = 0; i < novf; i++) {
            int4 e = g_ovf[i];
            if (e.x == side && e.y == row) {
                float val = __int_as_float(e.w);
                uint4 v = *reinterpret_cast<const uint4*>(
                    g_comb + (size_t)e.z * FT_OUT + lane * 8);
                float2 c0 = __half22float2(*reinterpret_cast<__half2*>(&v.x));
                float2 c1 = __half22float2(*reinterpret_cast<__half2*>(&v.y));
                float2 c2 = __half22float2(*reinterpret_cast<__half2*>(&v.z));
                float2 c3 = __half22float2(*reinterpret_cast<__half2*>(&v.w));
                acc[0] = fmaf(val, c0.x, acc[0]);
                acc[1] = fmaf(val, c0.y, acc[1]);
                acc[2] = fmaf(val, c1.x, acc[2]);
                acc[3] = fmaf(val, c1.y, acc[3]);
                acc[4] = fmaf(val, c2.x, acc[4]);
                acc[5] = fmaf(val, c2.y, acc[5]);
                acc[6] = fmaf(val, c3.x, acc[6]);
                acc[7] = fmaf(val, c3.y, acc[7]);
            }
        }
    }

    // Fused head: clip + dot with out_w segment for this side
    const float4* w4 = reinterpret_cast<const float4*>(out_w + side * FT_OUT) + lane * 2;
    float4 w0 = w4[0], w1 = w4[1];
    float dot = 0.0f;
    dot += fminf(fmaxf(acc[0], 0.0f), 1.0f) * w0.x;
    dot += fminf(fmaxf(acc[1], 0.0f), 1.0f) * w0.y;
    dot += fminf(fmaxf(acc[2], 0.0f), 1.0f) * w0.z;
    dot += fminf(fmaxf(acc[3], 0.0f), 1.0f) * w0.w;
    dot += fminf(fmaxf(acc[4], 0.0f), 1.0f) * w1.x;
    dot += fminf(fmaxf(acc[5], 0.0f), 1.0f) * w1.y;
    dot += fminf(fmaxf(acc[6], 0.0f), 1.0f) * w1.z;
    dot += fminf(fmaxf(acc[7], 0.0f), 1.0f) * w1.w;

    #pragma unroll
    for (int off = 16; off > 0; off >>= 1)
        dot += __shfl_down_sync(0xFFFFFFFFu, dot, off);
    if (lane == 0) g_partial[slot] = dot;
}

// ---------------------------------------------------------------------------
// Final: sigmoid(p_stm + p_nstm + out_b)
// ---------------------------------------------------------------------------
__global__ void final_kernel(const float* __restrict__ out_b,
                             float* __restrict__ out, int B) {
    int i = blockIdx.x * blockDim.x + threadIdx.x;
    if (i >= B) return;
    float z = g_partial[i] + g_partial[B + i] + out_b[0];
    out[i] = 1.0f / (1.0f + expf(-z));
}

// ---------------------------------------------------------------------------
// Launcher
// ---------------------------------------------------------------------------
extern "C" void kernel_launch(void* const* d_in, const int* in_sizes, int n_in,
                              void* d_out, int out_size) {
    const int*   stm_idx  = (const int*)d_in[0];
    const int*   nstm_idx = (const int*)d_in[1];
    const float* values   = (const float*)d_in[2];
    const float* ft_w     = (const float*)d_in[4];
    const float* ft_b     = (const float*)d_in[5];
    const float* fft_w    = (const float*)d_in[6];
    const float* fft_b    = (const float*)d_in[7];
    const float* out_w    = (const float*)d_in[8];
    const float* out_b    = (const float*)d_in[9];
    float* out = (float*)d_out;

    int NNZ = in_sizes[2];
    int B = out_size;
    if (B > B_MAX) B = B_MAX;

    dim3 blk(32, 8);

    // 1) fft transpose + zero counters + bias precompute
    prep_kernel<<<dim3(VFT_IN / 32, FT_OUT / 32), blk>>>(fft_w, ft_b, fft_b);

    // 2) combined fp16 table
    combine_kernel<<<dim3(FT_IN / 32, FT_OUT / 32), blk>>>(ft_w);

    // 3) bin (4 entries / thread)
    {
        int threads_total = (2 * NNZ) / 4;
        bin_kernel<<<(threads_total + 255) / 256, 256>>>(stm_idx, nstm_idx, values, NNZ, B);
    }

    // 4) accumulate + fused head dot (one warp per (side,row))
    accumulate_kernel<<<(2 * B * 32 + 255) / 256, 256>>>(out_w, B);

    // 5) final sigmoid
    final_kernel<<<(B + 255) / 256, 256>>>(out_b, out, B);
}

// round 13
// speedup vs baseline: 1.0086x; 1.0086x over previous
#include <cuda_runtime.h>
#include <cuda_fp16.h>
#include <cstdint>

#define FT_IN   40960
#define VFT_IN  640
#define FT_OUT  256
#define B_MAX   8192
#define CAP     128
#define OVF_MAX 4096

// -------- device-global scratch (no allocations allowed) --------
__device__ __half g_comb[(size_t)FT_IN * FT_OUT];   // [40960, 256] fp16: ftT + fftT[col%640]
__device__ float  g_fftT[(size_t)VFT_IN * FT_OUT];  // [640, 256]
__device__ float  g_bias[FT_OUT];                   // ft_b + fft_b
__device__ float  g_partial[2 * B_MAX];             // per-(side,row) dot partial
__device__ int    g_cnt[2 * B_MAX];
__device__ int2   g_bucket[2ULL * B_MAX * CAP];     // (col, val-bits)
__device__ int4   g_ovf[OVF_MAX];                   // (side, row, col, val-bits)
__device__ int    g_ovf_cnt;

// ---------------------------------------------------------------------------
// Prep: transpose fft_w [256,640] -> g_fftT [640,256]; zero counters; bias sum
// grid (20, 8) x block (32,8) = 40960 threads
// ---------------------------------------------------------------------------
__global__ void prep_kernel(const float* __restrict__ W,
                            const float* __restrict__ ft_b,
                            const float* __restrict__ fft_b) {
    __shared__ float tile[32][33];
    int colTile = blockIdx.x * 32;   // over 640
    int rowTile = blockIdx.y * 32;   // over 256
    int tx = threadIdx.x, ty = threadIdx.y;

    // folded housekeeping
    int gid = (blockIdx.y * gridDim.x + blockIdx.x) * 256 + ty * 32 + tx;
    if (gid < 2 * B_MAX) g_cnt[gid] = 0;
    if (gid == 0) g_ovf_cnt = 0;
    if (gid < FT_OUT) g_bias[gid] = ft_b[gid] + fft_b[gid];

    #pragma unroll
    for (int i = 0; i < 32; i += 8)
        tile[ty + i][tx] = W[(size_t)(rowTile + ty + i) * VFT_IN + colTile + tx];
    __syncthreads();
    #pragma unroll
    for (int i = 0; i < 32; i += 8) {
        int c = colTile + ty + i;
        int r = rowTile + tx;
        g_fftT[(size_t)c * FT_OUT + r] = tile[tx][ty + i];
    }
}

// ---------------------------------------------------------------------------
// Combine: transpose ft_w [256,40960] -> g_comb [40960,256] fp16,
// adding g_fftT[col%640]. half2 paired stores (4B coalesced).
// ---------------------------------------------------------------------------
__global__ void combine_kernel(const float* __restrict__ W) {
    __shared__ float tile[32][33];
    int colTile = blockIdx.x * 32;   // over 40960
    int rowTile = blockIdx.y * 32;   // over 256
    int tx = threadIdx.x, ty = threadIdx.y;
    #pragma unroll
    for (int i = 0; i < 32; i += 8)
        tile[ty + i][tx] = W[(size_t)(rowTile + ty + i) * FT_IN + colTile + tx];
    __syncthreads();

    int t = ty * 32 + tx;            // 0..255
    #pragma unroll
    for (int iter = 0; iter < 2; iter++) {
        int p  = t + iter * 256;     // 0..511 : 32 cols x 16 row-pairs
        int cl = p >> 4;             // column-local 0..31
        int rp = p & 15;             // row-pair 0..15
        int c  = colTile + cl;
        int r0 = rp * 2;             // local row (even)
        int cm = c % VFT_IN;
        float2 f = *reinterpret_cast<const float2*>(
            &g_fftT[(size_t)cm * FT_OUT + rowTile + r0]);
        __half2 h = __floats2half2_rn(tile[r0][cl] + f.x, tile[r0 + 1][cl] + f.y);
        *reinterpret_cast<__half2*>(&g_comb[(size_t)c * FT_OUT + rowTile + r0]) = h;
    }
}

// ---------------------------------------------------------------------------
// Binning: 4 entries per thread (int4/float4 loads) for MLP on the atomics
// ---------------------------------------------------------------------------
__global__ void bin_kernel(const int* __restrict__ stm_idx,
                           const int* __restrict__ nstm_idx,
                           const float* __restrict__ values,
                           int NNZ, int B) {
    int t = blockIdx.x * blockDim.x + threadIdx.x;
    int per_side = NNZ >> 2;
    if (t >= 2 * per_side) return;
    int side = (t >= per_side) ? 1 : 0;
    int base = (t - side * per_side) * 4;
    const int* idx = side ? nstm_idx : stm_idx;

    int4   rows = *reinterpret_cast<const int4*>(idx + base);
    int4   cols = *reinterpret_cast<const int4*>(idx + NNZ + base);
    float4 vals = *reinterpret_cast<const float4*>(values + base);

    int s0 = side * B + rows.x, s1 = side * B + rows.y;
    int s2 = side * B + rows.z, s3 = side * B + rows.w;
    int p0 = atomicAdd(&g_cnt[s0], 1);
    int p1 = atomicAdd(&g_cnt[s1], 1);
    int p2 = atomicAdd(&g_cnt[s2], 1);
    int p3 = atomicAdd(&g_cnt[s3], 1);

    if (p0 < CAP) g_bucket[(size_t)s0 * CAP + p0] = make_int2(cols.x, __float_as_int(vals.x));
    else { int o = atomicAdd(&g_ovf_cnt, 1); if (o < OVF_MAX) g_ovf[o] = make_int4(side, rows.x, cols.x, __float_as_int(vals.x)); }
    if (p1 < CAP) g_bucket[(size_t)s1 * CAP + p1] = make_int2(cols.y, __float_as_int(vals.y));
    else { int o = atomicAdd(&g_ovf_cnt, 1); if (o < OVF_MAX) g_ovf[o] = make_int4(side, rows.y, cols.y, __float_as_int(vals.y)); }
    if (p2 < CAP) g_bucket[(size_t)s2 * CAP + p2] = make_int2(cols.z, __float_as_int(vals.z));
    else { int o = atomicAdd(&g_ovf_cnt, 1); if (o < OVF_MAX) g_ovf[o] = make_int4(side, rows.z, cols.z, __float_as_int(vals.z)); }
    if (p3 < CAP) g_bucket[(size_t)s3 * CAP + p3] = make_int2(cols.w, __float_as_int(vals.w));
    else { int o = atomicAdd(&g_ovf_cnt, 1); if (o < OVF_MAX) g_ovf[o] = make_int4(side, rows.w, cols.w, __float_as_int(vals.w)); }
}

// ---------------------------------------------------------------------------
// Accumulate + fused head dot: one warp per (side,row).
// Lane owns 8 hidden units (one uint4 = 8 halves per column read).
// Entries broadcast across the warp via shfl, batches of 32.
// ---------------------------------------------------------------------------
__global__ void accumulate_kernel(const float* __restrict__ out_w, int B) {
    int warp_global = (blockIdx.x * blockDim.x + threadIdx.x) >> 5;
    int lane = threadIdx.x & 31;
    if (warp_global >= 2 * B) return;
    int slot = warp_global;
    int side = (slot >= B) ? 1 : 0;
    int row  = slot - side * B;

    int n = g_cnt[slot];
    if (n > CAP) n = CAP;

    float acc[8];
    {
        float4 b0 = *(reinterpret_cast<const float4*>(g_bias) + lane * 2);
        float4 b1 = *(reinterpret_cast<const float4*>(g_bias) + lane * 2 + 1);
        acc[0] = b0.x; acc[1] = b0.y; acc[2] = b0.z; acc[3] = b0.w;
        acc[4] = b1.x; acc[5] = b1.y; acc[6] = b1.z; acc[7] = b1.w;
    }

    const int2* bucket = g_bucket + (size_t)slot * CAP;
    for (int base = 0; base < n; base += 32) {
        int m = n - base; if (m > 32) m = 32;
        int2 ent = (lane < m) ? bucket[base + lane] : make_int2(0, 0);
        for (int e = 0; e < m; e++) {
            int   col = __shfl_sync(0xFFFFFFFFu, ent.x, e);
            float val = __int_as_float(__shfl_sync(0xFFFFFFFFu, ent.y, e));
            uint4 v = *reinterpret_cast<const uint4*>(
                g_comb + (size_t)col * FT_OUT + lane * 8);
            float2 c0 = __half22float2(*reinterpret_cast<__half2*>(&v.x));
            float2 c1 = __half22float2(*reinterpret_cast<__half2*>(&v.y));
            float2 c2 = __half22float2(*reinterpret_cast<__half2*>(&v.z));
            float2 c3 = __half22float2(*reinterpret_cast<__half2*>(&v.w));
            acc[0] = fmaf(val, c0.x, acc[0]);
            acc[1] = fmaf(val, c0.y, acc[1]);
            acc[2] = fmaf(val, c1.x, acc[2]);
            acc[3] = fmaf(val, c1.y, acc[3]);
            acc[4] = fmaf(val, c2.x, acc[4]);
            acc[5] = fmaf(val, c2.y, acc[5]);
            acc[6] = fmaf(val, c3.x, acc[6]);
            acc[7] = fmaf(val, c3.y, acc[7]);
        }
    }

    // Overflow fallback (normally g_ovf_cnt == 0)
    int novf = g_ovf_cnt;
    if (novf > 0) {
        if (novf > OVF_MAX) novf = OVF_MAX;
        for (int i = 0; i < novf; i++) {
            int4 e = g_ovf[i];
            if (e.x == side && e.y == row) {
                float val = __int_as_float(e.w);
                uint4 v = *reinterpret_cast<const uint4*>(
                    g_comb + (size_t)e.z * FT_OUT + lane * 8);
                float2 c0 = __half22float2(*reinterpret_cast<__half2*>(&v.x));
                float2 c1 = __half22float2(*reinterpret_cast<__half2*>(&v.y));
                float2 c2 = __half22float2(*reinterpret_cast<__half2*>(&v.z));
                float2 c3 = __half22float2(*reinterpret_cast<__half2*>(&v.w));
                acc[0] = fmaf(val, c0.x, acc[0]);
                acc[1] = fmaf(val, c0.y, acc[1]);
                acc[2] = fmaf(val, c1.x, acc[2]);
                acc[3] = fmaf(val, c1.y, acc[3]);
                acc[4] = fmaf(val, c2.x, acc[4]);
                acc[5] = fmaf(val, c2.y, acc[5]);
                acc[6] = fmaf(val, c3.x, acc[6]);
                acc[7] = fmaf(val, c3.y, acc[7]);
            }
        }
    }

    // Fused head: clip + dot with out_w segment for this side
    const float4* w4 = reinterpret_cast<const float4*>(out_w + side * FT_OUT) + lane * 2;
    float4 w0 = w4[0], w1 = w4[1];
    float dot = 0.0f;
    dot += fminf(fmaxf(acc[0], 0.0f), 1.0f) * w0.x;
    dot += fminf(fmaxf(acc[1], 0.0f), 1.0f) * w0.y;
    dot += fminf(fmaxf(acc[2], 0.0f), 1.0f) * w0.z;
    dot += fminf(fmaxf(acc[3], 0.0f), 1.0f) * w0.w;
    dot += fminf(fmaxf(acc[4], 0.0f), 1.0f) * w1.x;
    dot += fminf(fmaxf(acc[5], 0.0f), 1.0f) * w1.y;
    dot += fminf(fmaxf(acc[6], 0.0f), 1.0f) * w1.z;
    dot += fminf(fmaxf(acc[7], 0.0f), 1.0f) * w1.w;

    #pragma unroll
    for (int off = 16; off > 0; off >>= 1)
        dot += __shfl_down_sync(0xFFFFFFFFu, dot, off);
    if (lane == 0) g_partial[slot] = dot;
}

// ---------------------------------------------------------------------------
// Final: sigmoid(p_stm + p_nstm + out_b)
// ---------------------------------------------------------------------------
__global__ void final_kernel(const float* __restrict__ out_b,
                             float* __restrict__ out, int B) {
    int i = blockIdx.x * blockDim.x + threadIdx.x;
    if (i >= B) return;
    float z = g_partial[i] + g_partial[B + i] + out_b[0];
    out[i] = 1.0f / (1.0f + expf(-z));
}

// ---------------------------------------------------------------------------
// Launcher
// ---------------------------------------------------------------------------
extern "C" void kernel_launch(void* const* d_in, const int* in_sizes, int n_in,
                              void* d_out, int out_size) {
    const int*   stm_idx  = (const int*)d_in[0];
    const int*   nstm_idx = (const int*)d_in[1];
    const float* values   = (const float*)d_in[2];
    const float* ft_w     = (const float*)d_in[4];
    const float* ft_b     = (const float*)d_in[5];
    const float* fft_w    = (const float*)d_in[6];
    const float* fft_b    = (const float*)d_in[7];
    const float* out_w    = (const float*)d_in[8];
    const float* out_b    = (const float*)d_in[9];
    float* out = (float*)d_out;

    int NNZ = in_sizes[2];
    int B = out_size;
    if (B > B_MAX) B = B_MAX;

    dim3 blk(32, 8);

    // 1) fft transpose + zero counters + bias precompute
    prep_kernel<<<dim3(VFT_IN / 32, FT_OUT / 32), blk>>>(fft_w, ft_b, fft_b);

    // 2) combined fp16 table
    combine_kernel<<<dim3(FT_IN / 32, FT_OUT / 32), blk>>>(ft_w);

    // 3) bin (4 entries / thread)
    {
        int threads_total = (2 * NNZ) / 4;
        bin_kernel<<<(threads_total + 255) / 256, 256>>>(stm_idx, nstm_idx, values, NNZ, B);
    }

    // 4) accumulate + fused head dot (one warp per (side,row))
    accumulate_kernel<<<(2 * B * 32 + 255) / 256, 256>>>(out_w, B);

    // 5) final sigmoid
    final_kernel<<<(B + 255) / 256, 256>>>(out_b, out, B);
}